// round 1
// baseline (speedup 1.0000x reference)
#include <cuda_runtime.h>
#include <cstdint>

#define B_    4096
#define FIN   64
#define NK    512
#define FOUT  256
#define TB    32          // batch rows per block
#define XPITCH 68         // padded row pitch (floats) for conflict-free LDS.128

// -------- device scratch (no allocations allowed) --------
__device__ float g_Wt[NK * FOUT];   // W transposed: Wt[k][o]
__device__ float g_cc[NK];          // ||c_k||^2
__device__ float g_s2[NK];          // exp(2*log_shape_k)
__device__ float g_xx[B_];          // ||x_b||^2

// -------- prep kernels --------
__global__ void prep_centers(const float* __restrict__ centers,
                             const float* __restrict__ ls) {
    int k = threadIdx.x;
    if (k < NK) {
        const float* row = centers + k * FIN;
        float s = 0.f;
        #pragma unroll
        for (int f = 0; f < FIN; f++) { float v = row[f]; s = fmaf(v, v, s); }
        g_cc[k] = s;
        g_s2[k] = __expf(2.f * ls[k]);
    }
}

__global__ void prep_xx(const float* __restrict__ x) {
    int warp = threadIdx.x >> 5, lane = threadIdx.x & 31;
    int row = blockIdx.x * 8 + warp;
    float v0 = x[row * FIN + lane];
    float v1 = x[row * FIN + 32 + lane];
    float s = v0 * v0 + v1 * v1;
    #pragma unroll
    for (int off = 16; off; off >>= 1) s += __shfl_xor_sync(0xffffffffu, s, off);
    if (lane == 0) g_xx[row] = s;
}

// tiled transpose: W[256][512] -> g_Wt[512][256], both sides coalesced
__global__ void transpose_w(const float* __restrict__ W) {
    __shared__ float t[32][33];
    int kb = blockIdx.x * 32;   // k tile (16 tiles)
    int ob = blockIdx.y * 32;   // o tile (8 tiles)
    int tx = threadIdx.x, ty = threadIdx.y;
    #pragma unroll
    for (int i = 0; i < 32; i += 8)
        t[ty + i][tx] = W[(ob + ty + i) * NK + kb + tx];   // t[o_local][k_local]
    __syncthreads();
    #pragma unroll
    for (int i = 0; i < 32; i += 8)
        g_Wt[(kb + ty + i) * FOUT + ob + tx] = t[tx][ty + i];
}

// -------- fused main kernel --------
// smem layout (floats): rbfT[512*32] | s_x[32*68] | s_c[32*68] | cc[512] | s2[512]
//                       | xx[32] | inv[32] | part[256]
#define SMEM_FLOATS (NK*32 + TB*XPITCH + 32*XPITCH + NK + NK + 32 + 32 + 256)
#define SMEM_BYTES  (SMEM_FLOATS * 4)

__global__ __launch_bounds__(256, 1)
void rbf_main(const float* __restrict__ x,
              const float* __restrict__ centers,
              float* __restrict__ out) {
    extern __shared__ float sm[];
    float* s_rbfT = sm;                       // [k][row], 512x32, 128B-aligned rows
    float* s_x    = s_rbfT + NK * 32;
    float* s_c    = s_x + TB * XPITCH;
    float* s_cc   = s_c + 32 * XPITCH;
    float* s_s2   = s_cc + NK;
    float* s_xx   = s_s2 + NK;
    float* s_inv  = s_xx + 32;
    float* s_part = s_inv + 32;

    const int tid  = threadIdx.x;
    const int lane = tid & 31;
    const int warp = tid >> 5;
    const int b0   = blockIdx.x * TB;

    // stage input tile + per-k constants
    const float4* x4 = (const float4*)(x + (size_t)b0 * FIN);
    for (int i = tid; i < TB * 16; i += 256) {
        int r = i >> 4, c = i & 15;
        *(float4*)&s_x[r * XPITCH + c * 4] = x4[i];
    }
    for (int i = tid; i < NK; i += 256) { s_cc[i] = g_cc[i]; s_s2[i] = g_s2[i]; }
    if (tid < TB) s_xx[tid] = g_xx[b0 + tid];
    __syncthreads();

    const float xxrow = s_xx[lane];
    const float4* c4 = (const float4*)centers;

    // ---- phase 1: rbfT[k][row] = exp(-s2_k * (xx + cc_k - 2*dot)) ----
    for (int p = 0; p < 16; p++) {
        const int k0 = p * 32;
        __syncthreads();   // protect s_c of previous pass
        for (int i = tid; i < 32 * 16; i += 256) {
            int r = i >> 4, c = i & 15;
            *(float4*)&s_c[r * XPITCH + c * 4] = c4[(k0 + r) * 16 + c];
        }
        __syncthreads();

        const int klocal = warp << 2;       // 4 centers per warp
        float a0 = 0.f, a1 = 0.f, a2 = 0.f, a3 = 0.f;
        const float* xp  = s_x + lane * XPITCH;
        const float* cp0 = s_c + klocal * XPITCH;
        #pragma unroll
        for (int fc = 0; fc < 16; fc++) {
            float4 xv = *(const float4*)(xp + fc * 4);
            float4 v0 = *(const float4*)(cp0 + 0 * XPITCH + fc * 4);
            float4 v1 = *(const float4*)(cp0 + 1 * XPITCH + fc * 4);
            float4 v2 = *(const float4*)(cp0 + 2 * XPITCH + fc * 4);
            float4 v3 = *(const float4*)(cp0 + 3 * XPITCH + fc * 4);
            a0 = fmaf(xv.x, v0.x, a0); a0 = fmaf(xv.y, v0.y, a0);
            a0 = fmaf(xv.z, v0.z, a0); a0 = fmaf(xv.w, v0.w, a0);
            a1 = fmaf(xv.x, v1.x, a1); a1 = fmaf(xv.y, v1.y, a1);
            a1 = fmaf(xv.z, v1.z, a1); a1 = fmaf(xv.w, v1.w, a1);
            a2 = fmaf(xv.x, v2.x, a2); a2 = fmaf(xv.y, v2.y, a2);
            a2 = fmaf(xv.z, v2.z, a2); a2 = fmaf(xv.w, v2.w, a2);
            a3 = fmaf(xv.x, v3.x, a3); a3 = fmaf(xv.y, v3.y, a3);
            a3 = fmaf(xv.z, v3.z, a3); a3 = fmaf(xv.w, v3.w, a3);
        }
        const int kg = k0 + klocal;
        float r2;
        r2 = fmaf(-2.f, a0, xxrow + s_cc[kg + 0]);
        s_rbfT[(kg + 0) * 32 + lane] = __expf(-s_s2[kg + 0] * r2);
        r2 = fmaf(-2.f, a1, xxrow + s_cc[kg + 1]);
        s_rbfT[(kg + 1) * 32 + lane] = __expf(-s_s2[kg + 1] * r2);
        r2 = fmaf(-2.f, a2, xxrow + s_cc[kg + 2]);
        s_rbfT[(kg + 2) * 32 + lane] = __expf(-s_s2[kg + 2] * r2);
        r2 = fmaf(-2.f, a3, xxrow + s_cc[kg + 3]);
        s_rbfT[(kg + 3) * 32 + lane] = __expf(-s_s2[kg + 3] * r2);
    }
    __syncthreads();

    // ---- phase 2: row sums -> 1/(1e-9 + sum), folded into epilogue ----
    {
        float p0 = 0.f, p1 = 0.f, p2 = 0.f, p3 = 0.f;
        const int kb = warp * 64;
        #pragma unroll 4
        for (int k = 0; k < 64; k += 4) {
            p0 += s_rbfT[(kb + k + 0) * 32 + lane];
            p1 += s_rbfT[(kb + k + 1) * 32 + lane];
            p2 += s_rbfT[(kb + k + 2) * 32 + lane];
            p3 += s_rbfT[(kb + k + 3) * 32 + lane];
        }
        s_part[warp * 32 + lane] = (p0 + p1) + (p2 + p3);
    }
    __syncthreads();
    if (tid < 32) {
        float t = 1e-9f;
        #pragma unroll
        for (int w = 0; w < 8; w++) t += s_part[w * 32 + tid];
        s_inv[tid] = 1.f / t;
    }
    __syncthreads();

    // ---- phase 3: out[b0..b0+31][o] = (rbf @ Wt) * inv, packed f32x2 FMA ----
    unsigned long long acc[16];
    #pragma unroll
    for (int i = 0; i < 16; i++) acc[i] = 0ULL;

    const float* Wtp = g_Wt + tid;           // coalesced column o = tid
    #pragma unroll 2
    for (int k = 0; k < NK; k++) {
        float w = __ldg(&Wtp[k * FOUT]);
        unsigned long long ww;
        asm("mov.b64 %0, {%1, %1};" : "=l"(ww) : "f"(w));
        const ulonglong2* pr = (const ulonglong2*)(s_rbfT + (k << 5));
        #pragma unroll
        for (int m = 0; m < 8; m++) {
            ulonglong2 q = pr[m];            // 4 rbf floats = 2 packed f32x2 (broadcast LDS.128)
            asm("fma.rn.f32x2 %0, %1, %2, %0;" : "+l"(acc[2 * m + 0]) : "l"(q.x), "l"(ww));
            asm("fma.rn.f32x2 %0, %1, %2, %0;" : "+l"(acc[2 * m + 1]) : "l"(q.y), "l"(ww));
        }
    }

    #pragma unroll
    for (int i = 0; i < 16; i++) {
        float lo, hi;
        asm("mov.b64 {%0, %1}, %2;" : "=f"(lo), "=f"(hi) : "l"(acc[i]));
        out[(size_t)(b0 + 2 * i + 0) * FOUT + tid] = lo * s_inv[2 * i + 0];
        out[(size_t)(b0 + 2 * i + 1) * FOUT + tid] = hi * s_inv[2 * i + 1];
    }
}

// -------- launch --------
extern "C" void kernel_launch(void* const* d_in, const int* in_sizes, int n_in,
                              void* d_out, int out_size) {
    const float* x       = (const float*)d_in[0];  // [4096, 64]
    const float* W       = (const float*)d_in[1];  // [256, 512]
    const float* centers = (const float*)d_in[2];  // [512, 64]
    const float* ls      = (const float*)d_in[3];  // [512]
    float* out = (float*)d_out;                    // [4096, 256]

    cudaFuncSetAttribute(rbf_main, cudaFuncAttributeMaxDynamicSharedMemorySize, SMEM_BYTES);

    prep_centers<<<1, 512>>>(centers, ls);
    prep_xx<<<B_ / 8, 256>>>(x);
    transpose_w<<<dim3(16, 8), dim3(32, 8)>>>(W);
    rbf_main<<<B_ / TB, 256, SMEM_BYTES>>>(x, centers, out);
}

// round 2
// speedup vs baseline: 1.3243x; 1.3243x over previous
#include <cuda_runtime.h>
#include <cstdint>

#define B_    4096
#define FIN   64
#define NK    512
#define FOUT  256
#define TB    32
#define NTHR  512
#define XP    68            // padded pitch (floats) for conflict-free strided LDS.128

// -------- device scratch --------
__device__ float g_cc[NK];          // ||c_k||^2
__device__ float g_s2[NK];          // exp(2*log_shape_k)

// -------- smem layout (float offsets) --------
#define SM_RBF   0                       // rbfT [NK][32]
#define SM_X     (SM_RBF + NK*32)        // x    [32][XP]
#define SM_C     (SM_X   + 32*XP)        // c    [2][64][XP] double-buffered
#define SM_CC    (SM_C   + 2*64*XP)
#define SM_S2    (SM_CC  + NK)
#define SM_XX    (SM_S2  + NK)
#define SM_INV   (SM_XX  + 32)
#define SM_PART  (SM_INV + 32)           // [16][32]
#define SM_TOT   (SM_PART + 16*32)
#define SMEM_BYTES (SM_TOT * 4)

__device__ __forceinline__ void cp16(uint32_t dst, const void* src) {
    asm volatile("cp.async.ca.shared.global [%0], [%1], 16;" :: "r"(dst), "l"(src));
}

// -------- prep: ||c||^2 and exp(2*ls), 16 blocks --------
__global__ void prep_centers(const float* __restrict__ centers,
                             const float* __restrict__ ls) {
    int kb = blockIdx.x * 32;
    int warp = threadIdx.x >> 5, lane = threadIdx.x & 31;
    #pragma unroll
    for (int c = warp; c < 32; c += 8) {
        int k = kb + c;
        float v0 = centers[k * FIN + lane];
        float v1 = centers[k * FIN + 32 + lane];
        float s = fmaf(v0, v0, v1 * v1);
        #pragma unroll
        for (int off = 16; off; off >>= 1) s += __shfl_xor_sync(0xffffffffu, s, off);
        if (lane == 0) g_cc[k] = s;
    }
    if (threadIdx.x < 32) g_s2[kb + threadIdx.x] = __expf(2.f * ls[kb + threadIdx.x]);
}

// -------- fused main kernel: 512 threads, 1 CTA/SM, grid 128 --------
__global__ __launch_bounds__(NTHR, 1)
void rbf_main(const float* __restrict__ x,
              const float* __restrict__ centers,
              const float* __restrict__ W,
              float* __restrict__ out) {
    extern __shared__ float sm[];
    float* s_rbf  = sm + SM_RBF;
    float* s_x    = sm + SM_X;
    float* s_cc   = sm + SM_CC;
    float* s_s2   = sm + SM_S2;
    float* s_xx   = sm + SM_XX;
    float* s_inv  = sm + SM_INV;
    float* s_part = sm + SM_PART;

    const int tid  = threadIdx.x;
    const int lane = tid & 31;
    const int warp = tid >> 5;
    const int b0   = blockIdx.x * TB;
    const uint32_t smem_u = (uint32_t)__cvta_generic_to_shared(sm);

    // ---- stage x tile (one float4 per thread), cc/s2 ----
    {
        const float4* x4 = (const float4*)(x + (size_t)b0 * FIN);
        int r = tid >> 4, c = tid & 15;
        *(float4*)&s_x[r * XP + c * 4] = x4[r * 16 + c];
        s_cc[tid] = g_cc[tid];
        s_s2[tid] = g_s2[tid];
    }

    // ---- issue cp.async for center pass 0 (buf 0) ----
    {
        const float4* src = (const float4*)centers;
        #pragma unroll
        for (int i = tid; i < 1024; i += NTHR) {
            int r = i >> 4, c = i & 15;
            cp16(smem_u + (SM_C + r * XP + c * 4) * 4, src + i);
        }
        asm volatile("cp.async.commit_group;" ::: "memory");
    }
    __syncthreads();

    // ---- ||x||^2 per row (32 threads; others will wait on cp.async anyway) ----
    if (tid < 32) {
        const float4* xr = (const float4*)&s_x[tid * XP];
        float s = 0.f;
        #pragma unroll
        for (int f = 0; f < 16; f++) {
            float4 v = xr[f];
            s = fmaf(v.x, v.x, s); s = fmaf(v.y, v.y, s);
            s = fmaf(v.z, v.z, s); s = fmaf(v.w, v.w, s);
        }
        s_xx[tid] = s;
    }

    // ---- phase 1: 8 passes x 64 centers, double-buffered cp.async ----
    int buf = 0;
    for (int p = 0; p < 8; p++) {
        if (p < 7) {
            const float4* src = (const float4*)(centers + (p + 1) * 64 * FIN);
            int nb = buf ^ 1;
            #pragma unroll
            for (int i = tid; i < 1024; i += NTHR) {
                int r = i >> 4, c = i & 15;
                cp16(smem_u + (SM_C + nb * 64 * XP + r * XP + c * 4) * 4, src + i);
            }
            asm volatile("cp.async.commit_group;" ::: "memory");
            asm volatile("cp.async.wait_group 1;" ::: "memory");
        } else {
            asm volatile("cp.async.wait_group 0;" ::: "memory");
        }
        __syncthreads();   // buf data visible to all

        // each warp: 4 centers, lane = batch row; packed f32x2 dot products
        const float* cb = sm + SM_C + buf * 64 * XP + (warp * 4) * XP;
        const float* xp = &s_x[lane * XP];
        unsigned long long a0 = 0, a1 = 0, a2 = 0, a3 = 0;
        #pragma unroll
        for (int fc = 0; fc < 16; fc++) {
            ulonglong2 xv = *(const ulonglong2*)(xp + fc * 4);
            ulonglong2 c0 = *(const ulonglong2*)(cb + 0 * XP + fc * 4);
            ulonglong2 c1 = *(const ulonglong2*)(cb + 1 * XP + fc * 4);
            ulonglong2 c2 = *(const ulonglong2*)(cb + 2 * XP + fc * 4);
            ulonglong2 c3 = *(const ulonglong2*)(cb + 3 * XP + fc * 4);
            asm("fma.rn.f32x2 %0, %1, %2, %0;" : "+l"(a0) : "l"(xv.x), "l"(c0.x));
            asm("fma.rn.f32x2 %0, %1, %2, %0;" : "+l"(a0) : "l"(xv.y), "l"(c0.y));
            asm("fma.rn.f32x2 %0, %1, %2, %0;" : "+l"(a1) : "l"(xv.x), "l"(c1.x));
            asm("fma.rn.f32x2 %0, %1, %2, %0;" : "+l"(a1) : "l"(xv.y), "l"(c1.y));
            asm("fma.rn.f32x2 %0, %1, %2, %0;" : "+l"(a2) : "l"(xv.x), "l"(c2.x));
            asm("fma.rn.f32x2 %0, %1, %2, %0;" : "+l"(a2) : "l"(xv.y), "l"(c2.y));
            asm("fma.rn.f32x2 %0, %1, %2, %0;" : "+l"(a3) : "l"(xv.x), "l"(c3.x));
            asm("fma.rn.f32x2 %0, %1, %2, %0;" : "+l"(a3) : "l"(xv.y), "l"(c3.y));
        }
        const int kg = p * 64 + warp * 4;
        const float xxr = s_xx[lane];
        {
            float lo, hi, dot, r2;
            asm("mov.b64 {%0,%1}, %2;" : "=f"(lo), "=f"(hi) : "l"(a0));
            dot = lo + hi;
            r2 = fmaf(-2.f, dot, xxr + s_cc[kg + 0]);
            s_rbf[((kg + 0) << 5) + lane] = __expf(-s_s2[kg + 0] * r2);
            asm("mov.b64 {%0,%1}, %2;" : "=f"(lo), "=f"(hi) : "l"(a1));
            dot = lo + hi;
            r2 = fmaf(-2.f, dot, xxr + s_cc[kg + 1]);
            s_rbf[((kg + 1) << 5) + lane] = __expf(-s_s2[kg + 1] * r2);
            asm("mov.b64 {%0,%1}, %2;" : "=f"(lo), "=f"(hi) : "l"(a2));
            dot = lo + hi;
            r2 = fmaf(-2.f, dot, xxr + s_cc[kg + 2]);
            s_rbf[((kg + 2) << 5) + lane] = __expf(-s_s2[kg + 2] * r2);
            asm("mov.b64 {%0,%1}, %2;" : "=f"(lo), "=f"(hi) : "l"(a3));
            dot = lo + hi;
            r2 = fmaf(-2.f, dot, xxr + s_cc[kg + 3]);
            s_rbf[((kg + 3) << 5) + lane] = __expf(-s_s2[kg + 3] * r2);
        }
        __syncthreads();   // all reads of buf done before it is refilled next pass
        buf ^= 1;
    }

    // ---- phase 2: row sums -> 1/(1e-9 + sum) ----
    {
        float s0 = 0.f, s1 = 0.f;
        const int kb = warp * 32;
        #pragma unroll
        for (int k = 0; k < 32; k += 2) {
            s0 += s_rbf[((kb + k) << 5) + lane];
            s1 += s_rbf[((kb + k + 1) << 5) + lane];
        }
        s_part[(warp << 5) + lane] = s0 + s1;
    }
    __syncthreads();
    if (tid < 32) {
        float t = 1e-9f;
        #pragma unroll
        for (int w = 0; w < 16; w++) t += s_part[(w << 5) + tid];
        s_inv[tid] = 1.f / t;
    }
    __syncthreads();

    // ---- phase 3: out = (rbf @ W^T) * inv ; thread = (o, row-half) ----
    const int o  = tid & 255;
    const int rb = (tid >> 8) << 4;            // 0 or 16
    const float4* wp = (const float4*)(W + (size_t)o * NK);  // contiguous k stream

    unsigned long long acc[8];
    #pragma unroll
    for (int i = 0; i < 8; i++) acc[i] = 0ULL;

    float4 w4 = __ldg(&wp[0]);
    #pragma unroll 2
    for (int kk = 0; kk < 128; kk++) {
        int nx = kk + 1; if (nx > 127) nx = 127;
        float4 wn = __ldg(&wp[nx]);            // prefetch next 4 weights
        float wv[4] = {w4.x, w4.y, w4.z, w4.w};
        #pragma unroll
        for (int j = 0; j < 4; j++) {
            const int k = kk * 4 + j;
            unsigned long long ww;
            asm("mov.b64 %0, {%1, %1};" : "=l"(ww) : "f"(wv[j]));
            const ulonglong2* pr = (const ulonglong2*)(s_rbf + (k << 5) + rb);
            ulonglong2 q0 = pr[0], q1 = pr[1], q2 = pr[2], q3 = pr[3];
            asm("fma.rn.f32x2 %0, %1, %2, %0;" : "+l"(acc[0]) : "l"(q0.x), "l"(ww));
            asm("fma.rn.f32x2 %0, %1, %2, %0;" : "+l"(acc[1]) : "l"(q0.y), "l"(ww));
            asm("fma.rn.f32x2 %0, %1, %2, %0;" : "+l"(acc[2]) : "l"(q1.x), "l"(ww));
            asm("fma.rn.f32x2 %0, %1, %2, %0;" : "+l"(acc[3]) : "l"(q1.y), "l"(ww));
            asm("fma.rn.f32x2 %0, %1, %2, %0;" : "+l"(acc[4]) : "l"(q2.x), "l"(ww));
            asm("fma.rn.f32x2 %0, %1, %2, %0;" : "+l"(acc[5]) : "l"(q2.y), "l"(ww));
            asm("fma.rn.f32x2 %0, %1, %2, %0;" : "+l"(acc[6]) : "l"(q3.x), "l"(ww));
            asm("fma.rn.f32x2 %0, %1, %2, %0;" : "+l"(acc[7]) : "l"(q3.y), "l"(ww));
        }
        w4 = wn;
    }

    // ---- epilogue: normalize + store ----
    #pragma unroll
    for (int i = 0; i < 8; i++) {
        float lo, hi;
        asm("mov.b64 {%0,%1}, %2;" : "=f"(lo), "=f"(hi) : "l"(acc[i]));
        const int r0 = rb + 2 * i, r1 = rb + 2 * i + 1;
        out[(size_t)(b0 + r0) * FOUT + o] = lo * s_inv[r0];
        out[(size_t)(b0 + r1) * FOUT + o] = hi * s_inv[r1];
    }
}

// -------- launch --------
extern "C" void kernel_launch(void* const* d_in, const int* in_sizes, int n_in,
                              void* d_out, int out_size) {
    const float* x       = (const float*)d_in[0];  // [4096, 64]
    const float* W       = (const float*)d_in[1];  // [256, 512]
    const float* centers = (const float*)d_in[2];  // [512, 64]
    const float* ls      = (const float*)d_in[3];  // [512]
    float* out = (float*)d_out;                    // [4096, 256]

    cudaFuncSetAttribute(rbf_main, cudaFuncAttributeMaxDynamicSharedMemorySize, SMEM_BYTES);

    prep_centers<<<16, 256>>>(centers, ls);
    rbf_main<<<B_ / TB, NTHR, SMEM_BYTES>>>(x, centers, W, out);
}